// round 1
// baseline (speedup 1.0000x reference)
#include <cuda_runtime.h>
#include <cuda_bf16.h>
#include <cstdint>

// Problem constants
#define M_DIM 8192
#define K_DIM 7168
#define N_DIM 2112           // 1536 + 512 + 64
#define Q_RANK 1536
#define KV_RANK 512
#define ROPE_DIM 64
#define GROUP_SZ 128
#define N_GROUPS 12          // 1536 / 128
#define FP8_MAX 448.0f
#define EPS_RMS 1e-6f

// Output layout in d_out (flattened, concatenated in reference return order):
//   q_c_quant : [8192, 1536] at 0
//   q_c_scale : [8192, 12]   at 8192*1536
//   kv_normed : [8192, 512]  at +8192*12
//   k_pe      : [8192, 64]   at +8192*512
#define OUT_QQ   ((size_t)0)
#define OUT_SC   ((size_t)M_DIM * Q_RANK)
#define OUT_KV   (OUT_SC + (size_t)M_DIM * N_GROUPS)
#define OUT_KPE  (OUT_KV + (size_t)M_DIM * KV_RANK)

// Scratch for the full GEMM result (no cudaMalloc allowed -> device global)
__device__ __align__(16) float g_scratch[(size_t)M_DIM * N_DIM];

// ---------------------------------------------------------------------------
// GEMM: C[m,n] = sum_k A[m,k] * B[k,n]
// 128x128 block tile, BK=16, 256 threads, 8x8 per-thread microtile,
// double-buffered shared memory.
// ---------------------------------------------------------------------------
#define BM 128
#define BN 128
#define BK 16
#define KT (K_DIM / BK)      // 448
#define APAD 4               // pad A smem rows to kill store bank conflicts

__global__ __launch_bounds__(256, 2)
void gemm_kernel(const float* __restrict__ A, const float* __restrict__ B)
{
    __shared__ float As[2][BK][BM + APAD];   // [k][m], padded
    __shared__ float Bs[2][BK][BN];          // [k][n]

    const int tid = threadIdx.x;
    const int bm  = blockIdx.y * BM;
    const int bn  = blockIdx.x * BN;

    const int ty = tid >> 4;     // 0..15  -> rows ty*8..ty*8+7
    const int tx = tid & 15;     // 0..15  -> cols tx*8..tx*8+7

    // Load mappings (512 float4 per tile each for A and B; 2 per thread)
    // A: idx -> row = idx>>2 (0..127), kc = (idx&3)*4
    // B: idx -> krow = idx>>5 (0..15), col = (idx&31)*4
    float4 pa[2], pb[2];

    auto fetchA = [&](int kt) {
#pragma unroll
        for (int l = 0; l < 2; l++) {
            int idx = tid + l * 256;
            int r = idx >> 2, kc = (idx & 3) * 4;
            pa[l] = *reinterpret_cast<const float4*>(
                &A[(size_t)(bm + r) * K_DIM + kt * BK + kc]);
        }
    };
    auto fetchB = [&](int kt) {
#pragma unroll
        for (int l = 0; l < 2; l++) {
            int idx = tid + l * 256;
            int r = idx >> 5, c = (idx & 31) * 4;
            int gcol = bn + c;
            if (gcol < N_DIM) {   // N_DIM % 4 == 0 so float4 is all-in or all-out
                pb[l] = *reinterpret_cast<const float4*>(
                    &B[(size_t)(kt * BK + r) * N_DIM + gcol]);
            } else {
                pb[l] = make_float4(0.f, 0.f, 0.f, 0.f);
            }
        }
    };
    auto stash = [&](int buf) {
#pragma unroll
        for (int l = 0; l < 2; l++) {
            int idx = tid + l * 256;
            int r = idx >> 2, kc = (idx & 3) * 4;
            As[buf][kc + 0][r] = pa[l].x;
            As[buf][kc + 1][r] = pa[l].y;
            As[buf][kc + 2][r] = pa[l].z;
            As[buf][kc + 3][r] = pa[l].w;
            int br = idx >> 5, bc = (idx & 31) * 4;
            *reinterpret_cast<float4*>(&Bs[buf][br][bc]) = pb[l];
        }
    };

    float acc[8][8];
#pragma unroll
    for (int i = 0; i < 8; i++)
#pragma unroll
        for (int j = 0; j < 8; j++) acc[i][j] = 0.f;

    fetchA(0); fetchB(0);
    stash(0);
    __syncthreads();

    int buf = 0;
    for (int kt = 0; kt < KT; kt++) {
        if (kt + 1 < KT) { fetchA(kt + 1); fetchB(kt + 1); }

#pragma unroll
        for (int kk = 0; kk < BK; kk++) {
            float a[8], b[8];
            *reinterpret_cast<float4*>(&a[0]) =
                *reinterpret_cast<const float4*>(&As[buf][kk][ty * 8 + 0]);
            *reinterpret_cast<float4*>(&a[4]) =
                *reinterpret_cast<const float4*>(&As[buf][kk][ty * 8 + 4]);
            *reinterpret_cast<float4*>(&b[0]) =
                *reinterpret_cast<const float4*>(&Bs[buf][kk][tx * 8 + 0]);
            *reinterpret_cast<float4*>(&b[4]) =
                *reinterpret_cast<const float4*>(&Bs[buf][kk][tx * 8 + 4]);
#pragma unroll
            for (int i = 0; i < 8; i++)
#pragma unroll
                for (int j = 0; j < 8; j++)
                    acc[i][j] = fmaf(a[i], b[j], acc[i][j]);
        }

        if (kt + 1 < KT) {
            stash(buf ^ 1);
            __syncthreads();
            buf ^= 1;
        }
    }

    // Store C tile to scratch (guard N boundary; N%4==0 so float4-granular)
#pragma unroll
    for (int i = 0; i < 8; i++) {
        int row = bm + ty * 8 + i;
        float* crow = &g_scratch[(size_t)row * N_DIM];
#pragma unroll
        for (int j = 0; j < 8; j += 4) {
            int col = bn + tx * 8 + j;
            if (col < N_DIM) {
                float4 v = make_float4(acc[i][j], acc[i][j + 1],
                                       acc[i][j + 2], acc[i][j + 3]);
                *reinterpret_cast<float4*>(&crow[col]) = v;
            }
        }
    }
}

// ---------------------------------------------------------------------------
// Epilogue: one block per row. Dual RMSNorm + group amax quant + k_pe copy.
// ---------------------------------------------------------------------------
__global__ __launch_bounds__(256)
void epilogue_kernel(const float* __restrict__ wq,
                     const float* __restrict__ wkv,
                     float* __restrict__ out)
{
    const int m   = blockIdx.x;
    const int tid = threadIdx.x;
    const float* row = &g_scratch[(size_t)m * N_DIM];

    __shared__ float s_qn[Q_RANK];     // normalized q, pre-quant
    __shared__ float s_amax[N_GROUPS];
    __shared__ float s_red[16];
    __shared__ float s_rsq[2];

    if (tid < N_GROUPS) s_amax[tid] = 0.f;

    // Pass 1: sum of squares for q and kv slices; write k_pe passthrough.
    float qs = 0.f, kvs = 0.f;
    for (int i = tid; i < N_DIM / 4; i += 256) {
        float4 v = *reinterpret_cast<const float4*>(row + i * 4);
        int c = i * 4;
        float d = v.x * v.x + v.y * v.y + v.z * v.z + v.w * v.w;
        if (c < Q_RANK)                    qs  += d;
        else if (c < Q_RANK + KV_RANK)     kvs += d;
        else {
            *reinterpret_cast<float4*>(
                out + OUT_KPE + (size_t)m * ROPE_DIM + (c - Q_RANK - KV_RANK)) = v;
        }
    }
#pragma unroll
    for (int o = 16; o > 0; o >>= 1) {
        qs  += __shfl_down_sync(0xFFFFFFFFu, qs,  o);
        kvs += __shfl_down_sync(0xFFFFFFFFu, kvs, o);
    }
    int wid = tid >> 5, lane = tid & 31;
    if (lane == 0) { s_red[wid] = qs; s_red[8 + wid] = kvs; }
    __syncthreads();
    if (tid == 0) {
        float a = 0.f, b = 0.f;
#pragma unroll
        for (int w = 0; w < 8; w++) { a += s_red[w]; b += s_red[8 + w]; }
        s_rsq[0] = rsqrtf(a / (float)Q_RANK  + EPS_RMS);
        s_rsq[1] = rsqrtf(b / (float)KV_RANK + EPS_RMS);
    }
    __syncthreads();
    const float rq = s_rsq[0], rkv = s_rsq[1];

    // Pass 2a: q normalize -> smem, group amax via shared atomicMax (vals >= 0)
    for (int i = tid; i < Q_RANK / 4; i += 256) {
        int c = i * 4;
        float4 v = *reinterpret_cast<const float4*>(row + c);
        float4 w = *reinterpret_cast<const float4*>(wq + c);
        float4 q;
        q.x = v.x * rq * w.x;  q.y = v.y * rq * w.y;
        q.z = v.z * rq * w.z;  q.w = v.w * rq * w.w;
        *reinterpret_cast<float4*>(&s_qn[c]) = q;
        float am = fmaxf(fmaxf(fabsf(q.x), fabsf(q.y)),
                         fmaxf(fabsf(q.z), fabsf(q.w)));
        atomicMax(reinterpret_cast<int*>(&s_amax[c >> 7]), __float_as_int(am));
    }
    // Pass 2b: kv normalize -> out
    for (int i = tid; i < KV_RANK / 4; i += 256) {
        int c = i * 4;
        float4 v = *reinterpret_cast<const float4*>(row + Q_RANK + c);
        float4 w = *reinterpret_cast<const float4*>(wkv + c);
        float4 o;
        o.x = v.x * rkv * w.x;  o.y = v.y * rkv * w.y;
        o.z = v.z * rkv * w.z;  o.w = v.w * rkv * w.w;
        *reinterpret_cast<float4*>(out + OUT_KV + (size_t)m * KV_RANK + c) = o;
    }
    __syncthreads();

    // Scales
    if (tid < N_GROUPS) {
        float sc = fmaxf(s_amax[tid] / FP8_MAX, 1e-12f);
        s_amax[tid] = sc;
        out[OUT_SC + (size_t)m * N_GROUPS + tid] = sc;
    }
    __syncthreads();

    // Pass 3: quantize q
    for (int i = tid; i < Q_RANK / 4; i += 256) {
        int c = i * 4;
        float sc = s_amax[c >> 7];
        float inv = 1.0f / sc;
        float4 q = *reinterpret_cast<const float4*>(&s_qn[c]);
        float4 o;
        o.x = q.x * inv; o.y = q.y * inv; o.z = q.z * inv; o.w = q.w * inv;
        *reinterpret_cast<float4*>(out + OUT_QQ + (size_t)m * Q_RANK + c) = o;
    }
}

// ---------------------------------------------------------------------------
extern "C" void kernel_launch(void* const* d_in, const int* in_sizes, int n_in,
                              void* d_out, int out_size)
{
    const float* hidden = (const float*)d_in[0];   // [8192, 7168]
    const float* w_qkv  = (const float*)d_in[1];   // [7168, 2112]
    const float* wq     = (const float*)d_in[2];   // [1536]
    const float* wkv    = (const float*)d_in[3];   // [512]
    float* out = (float*)d_out;

    dim3 grid((N_DIM + BN - 1) / BN, M_DIM / BM);  // (17, 64)
    gemm_kernel<<<grid, 256>>>(hidden, w_qkv);
    epilogue_kernel<<<M_DIM, 256>>>(wq, wkv, out);
}

// round 3
// speedup vs baseline: 4.6274x; 4.6274x over previous
#include <cuda_runtime.h>
#include <cuda_bf16.h>
#include <cstdint>
#include <cstddef>

// ---------------- problem constants ----------------
#define M_DIM 8192
#define K_DIM 7168
#define N_DIM 2112           // 1536 + 512 + 64
#define Q_RANK 1536
#define KV_RANK 512
#define ROPE_DIM 64
#define N_GROUPS 12
#define FP8_MAX 448.0f
#define EPS_RMS 1e-6f

#define OUT_QQ   ((size_t)0)
#define OUT_SC   ((size_t)M_DIM * Q_RANK)
#define OUT_KV   (OUT_SC + (size_t)M_DIM * N_GROUPS)
#define OUT_KPE  (OUT_KV + (size_t)M_DIM * KV_RANK)

// ---------------- GEMM tiling ----------------
#define MT 128
#define NT 256
#define KB 64                        // bf16 elems per K slab (128 bytes per row)
#define NSLAB (K_DIM / KB)           // 112
#define N_PAD 2304                   // 9 * 256
#define STAGE_BYTES (96 * 1024)      // Ahi 16K | Alo 16K | Bhi 32K | Blo 32K
#define SMEM_TOTAL (2 * STAGE_BYTES)

// ---------------- device scratch (no cudaMalloc allowed) ----------------
__device__ __align__(1024) __nv_bfloat16 g_Ahi[(size_t)M_DIM * K_DIM];
__device__ __align__(1024) __nv_bfloat16 g_Alo[(size_t)M_DIM * K_DIM];
__device__ __align__(1024) __nv_bfloat16 g_Bhi[(size_t)N_PAD * K_DIM];   // [n][k] transposed
__device__ __align__(1024) __nv_bfloat16 g_Blo[(size_t)N_PAD * K_DIM];
__device__ __align__(16)   float         g_scratch[(size_t)M_DIM * N_DIM];

// ---------------- PTX helpers (baseline PTX only: sm_80-era) ----------------
__device__ __forceinline__ uint32_t smem_u32(const void* p) {
    uint32_t a;
    asm("{ .reg .u64 t; cvta.to.shared.u64 t, %1; cvt.u32.u64 %0, t; }" : "=r"(a) : "l"(p));
    return a;
}

__device__ __forceinline__ void cpa16(uint32_t dst, const void* src) {
    asm volatile("cp.async.cg.shared.global [%0], [%1], 16;" :: "r"(dst), "l"(src));
}
#define CP_COMMIT() asm volatile("cp.async.commit_group;" ::: "memory")
#define CP_WAIT1()  asm volatile("cp.async.wait_group 1;"  ::: "memory")

__device__ __forceinline__ void ldsm4(uint32_t* r, uint32_t addr) {
    asm volatile("ldmatrix.sync.aligned.m8n8.x4.shared.b16 {%0,%1,%2,%3}, [%4];"
                 : "=r"(r[0]), "=r"(r[1]), "=r"(r[2]), "=r"(r[3]) : "r"(addr));
}

__device__ __forceinline__ void mma16816(float* c, const uint32_t* a,
                                         uint32_t b0, uint32_t b1) {
    asm volatile(
        "mma.sync.aligned.m16n8k16.row.col.f32.bf16.bf16.f32 "
        "{%0,%1,%2,%3}, {%4,%5,%6,%7}, {%8,%9}, {%0,%1,%2,%3};"
        : "+f"(c[0]), "+f"(c[1]), "+f"(c[2]), "+f"(c[3])
        : "r"(a[0]), "r"(a[1]), "r"(a[2]), "r"(a[3]), "r"(b0), "r"(b1));
}

// ---------------------------------------------------------------------------
// fp32 -> bf16 hi/lo split of hidden_states
// ---------------------------------------------------------------------------
__global__ __launch_bounds__(256)
void convA_kernel(const float* __restrict__ A)
{
    size_t i = ((size_t)blockIdx.x * 256 + threadIdx.x) * 4;
    float4 v = *reinterpret_cast<const float4*>(A + i);
    __nv_bfloat16 h0 = __float2bfloat16(v.x), h1 = __float2bfloat16(v.y);
    __nv_bfloat16 h2 = __float2bfloat16(v.z), h3 = __float2bfloat16(v.w);
    __nv_bfloat16 l0 = __float2bfloat16(v.x - __bfloat162float(h0));
    __nv_bfloat16 l1 = __float2bfloat16(v.y - __bfloat162float(h1));
    __nv_bfloat16 l2 = __float2bfloat16(v.z - __bfloat162float(h2));
    __nv_bfloat16 l3 = __float2bfloat16(v.w - __bfloat162float(h3));
    __nv_bfloat162 a, b;
    a.x = h0; a.y = h1; b.x = h2; b.y = h3;
    *reinterpret_cast<__nv_bfloat162*>(&g_Ahi[i])     = a;
    *reinterpret_cast<__nv_bfloat162*>(&g_Ahi[i + 2]) = b;
    a.x = l0; a.y = l1; b.x = l2; b.y = l3;
    *reinterpret_cast<__nv_bfloat162*>(&g_Alo[i])     = a;
    *reinterpret_cast<__nv_bfloat162*>(&g_Alo[i + 2]) = b;
}

// ---------------------------------------------------------------------------
// w_qkv_a [K, N] -> transposed bf16 hi/lo [N_PAD, K] (pad rows zeroed)
// ---------------------------------------------------------------------------
__global__ __launch_bounds__(256)
void convB_kernel(const float* __restrict__ W)
{
    __shared__ float t[32][33];
    const int kt = blockIdx.y * 32;
    const int nt = blockIdx.x * 32;
    const int tx = threadIdx.x, ty = threadIdx.y;

#pragma unroll
    for (int j = 0; j < 4; j++) {
        int k = kt + ty + j * 8;
        int n = nt + tx;
        t[ty + j * 8][tx] = (n < N_DIM) ? W[(size_t)k * N_DIM + n] : 0.f;
    }
    __syncthreads();
#pragma unroll
    for (int j = 0; j < 4; j++) {
        int n = nt + ty + j * 8;
        int k = kt + tx;
        float v = t[tx][ty + j * 8];
        __nv_bfloat16 h = __float2bfloat16(v);
        __nv_bfloat16 l = __float2bfloat16(v - __bfloat162float(h));
        g_Bhi[(size_t)n * K_DIM + k] = h;
        g_Blo[(size_t)n * K_DIM + k] = l;
    }
}

// ---------------------------------------------------------------------------
// GEMM via mma.sync (HMMA): 128x256 block, 512 threads, warp tile 32x64,
// bf16 hi/lo 3-product, 2-stage cp.async pipeline, XOR-swizzled smem.
//
// Stage layout (768 rows x 128B):
//   rows   0-127 : Ahi  (offset 0)
//   rows 128-255 : Alo  (offset 16384)
//   rows 256-511 : Bhi  (offset 32768)
//   rows 512-767 : Blo  (offset 65536)
// Within a row, 16B chunk c stored at chunk (c ^ (row & 7)).
// ---------------------------------------------------------------------------
__global__ __launch_bounds__(512, 1)
void mma_gemm_kernel()
{
    extern __shared__ __align__(1024) char smem[];
    const uint32_t sbase = smem_u32(smem);
    const int tid  = threadIdx.x;
    const int bm   = blockIdx.y * MT;
    const int bn   = blockIdx.x * NT;
    const int lane = tid & 31;
    const int wid  = tid >> 5;           // 0..15
    const int wm   = wid & 3;            // m: 4 warps * 32
    const int wn   = wid >> 2;           // n: 4 warps * 64

    // ---- cooperative load setup: 12 x 16B per thread per stage ----
    const int rb    = tid >> 3;          // 0..63 (row within each 64-row unit)
    const int chunk = tid & 7;
    const uint32_t swc16 = (uint32_t)((chunk ^ (rb & 7)) << 4);
    const uint32_t dbase = sbase + (uint32_t)rb * 128 + swc16;

    const char* a0 = (const char*)(g_Ahi + (size_t)(bm + rb) * K_DIM) + chunk * 16;
    const char* a1 = a0 + (size_t)64 * K_DIM * 2;
    const char* b0 = (const char*)(g_Bhi + (size_t)(bn + rb) * K_DIM) + chunk * 16;
    const char* b1 = b0 + (size_t)64  * K_DIM * 2;
    const char* b2 = b0 + (size_t)128 * K_DIM * 2;
    const char* b3 = b0 + (size_t)192 * K_DIM * 2;
    const ptrdiff_t dAlo = (const char*)g_Alo - (const char*)g_Ahi;
    const ptrdiff_t dBlo = (const char*)g_Blo - (const char*)g_Bhi;

    auto load_stage = [&](uint32_t soff, size_t koff) {
        uint32_t d = dbase + soff;
        cpa16(d,             a0 + koff);
        cpa16(d + 8192,      a1 + koff);
        cpa16(d + 16384,     a0 + koff + dAlo);
        cpa16(d + 24576,     a1 + koff + dAlo);
        cpa16(d + 32768,     b0 + koff);
        cpa16(d + 40960,     b1 + koff);
        cpa16(d + 49152,     b2 + koff);
        cpa16(d + 57344,     b3 + koff);
        cpa16(d + 65536,     b0 + koff + dBlo);
        cpa16(d + 73728,     b1 + koff + dBlo);
        cpa16(d + 81920,     b2 + koff + dBlo);
        cpa16(d + 90112,     b3 + koff + dBlo);
    };

    // ---- ldmatrix address constants ----
    const int lr = lane & 15;            // row-within-16
    const int lh = lane >> 4;            // k-chunk half
    const int l7 = lr & 7;
    // A tiles (mt = 0,1): local m rows wm*32 + mt*16 + lr
    uint32_t rowA[2], rowB[4];
#pragma unroll
    for (int mt = 0; mt < 2; mt++)
        rowA[mt] = (uint32_t)((wm * 32 + mt * 16 + lr) * 128);
    // B pairs (p = 0..3): local n rows wn*64 + p*16 + lr, region offset +32768
#pragma unroll
    for (int p = 0; p < 4; p++)
        rowB[p] = (uint32_t)(32768 + (wn * 64 + p * 16 + lr) * 128);

    float acc[2][8][4];
#pragma unroll
    for (int mt = 0; mt < 2; mt++)
#pragma unroll
        for (int nt = 0; nt < 8; nt++)
#pragma unroll
            for (int r = 0; r < 4; r++) acc[mt][nt][r] = 0.f;

    // ---- pipeline ----
    load_stage(0, 0);
    CP_COMMIT();

    for (int s = 0; s < NSLAB; s++) {
        if (s + 1 < NSLAB)
            load_stage((uint32_t)((s + 1) & 1) * STAGE_BYTES, (size_t)(s + 1) * 128);
        CP_COMMIT();          // empty group when no loads issued (legal)
        CP_WAIT1();           // slab s resident
        __syncthreads();

        const uint32_t bs = sbase + (uint32_t)(s & 1) * STAGE_BYTES;
#pragma unroll
        for (int ks = 0; ks < 4; ks++) {
            const uint32_t sw = (uint32_t)(((2 * ks + lh) ^ l7) << 4);
            uint32_t aH[2][4], aL[2][4];
#pragma unroll
            for (int mt = 0; mt < 2; mt++) {
                ldsm4(aH[mt], bs + rowA[mt] + sw);
                ldsm4(aL[mt], bs + 16384 + rowA[mt] + sw);
            }
#pragma unroll
            for (int p = 0; p < 4; p++) {
                uint32_t bH[4], bL[4];
                ldsm4(bH, bs + rowB[p] + sw);
                ldsm4(bL, bs + 32768 + rowB[p] + sw);
#pragma unroll
                for (int mt = 0; mt < 2; mt++) {
#pragma unroll
                    for (int t = 0; t < 2; t++) {
                        float* c = acc[mt][2 * p + t];
                        mma16816(c, aH[mt], bH[t], bH[t + 2]);   // hi*hi
                        mma16816(c, aH[mt], bL[t], bL[t + 2]);   // hi*lo
                        mma16816(c, aL[mt], bH[t], bH[t + 2]);   // lo*hi
                    }
                }
            }
        }
        __syncthreads();
    }

    // ---- store accumulators to scratch ----
#pragma unroll
    for (int mt = 0; mt < 2; mt++) {
        const int row = bm + wm * 32 + mt * 16 + (lane >> 2);
#pragma unroll
        for (int nt = 0; nt < 8; nt++) {
            const int col = bn + wn * 64 + nt * 8 + (lane & 3) * 2;
            if (col < N_DIM) {
                float* p0 = &g_scratch[(size_t)row * N_DIM + col];
                float* p1 = &g_scratch[(size_t)(row + 8) * N_DIM + col];
                *reinterpret_cast<float2*>(p0) =
                    make_float2(acc[mt][nt][0], acc[mt][nt][1]);
                *reinterpret_cast<float2*>(p1) =
                    make_float2(acc[mt][nt][2], acc[mt][nt][3]);
            }
        }
    }
}

// ---------------------------------------------------------------------------
// Epilogue: one block per row. Dual RMSNorm + group amax quant + k_pe copy.
// ---------------------------------------------------------------------------
__global__ __launch_bounds__(256)
void epilogue_kernel(const float* __restrict__ wq,
                     const float* __restrict__ wkv,
                     float* __restrict__ out)
{
    const int m   = blockIdx.x;
    const int tid = threadIdx.x;
    const float* row = &g_scratch[(size_t)m * N_DIM];

    __shared__ float s_qn[Q_RANK];
    __shared__ float s_amax[N_GROUPS];
    __shared__ float s_red[16];
    __shared__ float s_rsq[2];

    if (tid < N_GROUPS) s_amax[tid] = 0.f;

    float qs = 0.f, kvs = 0.f;
    for (int i = tid; i < N_DIM / 4; i += 256) {
        float4 v = *reinterpret_cast<const float4*>(row + i * 4);
        int c = i * 4;
        float d = v.x * v.x + v.y * v.y + v.z * v.z + v.w * v.w;
        if (c < Q_RANK)                qs  += d;
        else if (c < Q_RANK + KV_RANK) kvs += d;
        else {
            *reinterpret_cast<float4*>(
                out + OUT_KPE + (size_t)m * ROPE_DIM + (c - Q_RANK - KV_RANK)) = v;
        }
    }
#pragma unroll
    for (int o = 16; o > 0; o >>= 1) {
        qs  += __shfl_down_sync(0xFFFFFFFFu, qs,  o);
        kvs += __shfl_down_sync(0xFFFFFFFFu, kvs, o);
    }
    int wid = tid >> 5, lane = tid & 31;
    if (lane == 0) { s_red[wid] = qs; s_red[8 + wid] = kvs; }
    __syncthreads();
    if (tid == 0) {
        float a = 0.f, b = 0.f;
#pragma unroll
        for (int w = 0; w < 8; w++) { a += s_red[w]; b += s_red[8 + w]; }
        s_rsq[0] = rsqrtf(a / (float)Q_RANK  + EPS_RMS);
        s_rsq[1] = rsqrtf(b / (float)KV_RANK + EPS_RMS);
    }
    __syncthreads();
    const float rq = s_rsq[0], rkv = s_rsq[1];

    for (int i = tid; i < Q_RANK / 4; i += 256) {
        int c = i * 4;
        float4 v = *reinterpret_cast<const float4*>(row + c);
        float4 w = *reinterpret_cast<const float4*>(wq + c);
        float4 q;
        q.x = v.x * rq * w.x;  q.y = v.y * rq * w.y;
        q.z = v.z * rq * w.z;  q.w = v.w * rq * w.w;
        *reinterpret_cast<float4*>(&s_qn[c]) = q;
        float am = fmaxf(fmaxf(fabsf(q.x), fabsf(q.y)),
                         fmaxf(fabsf(q.z), fabsf(q.w)));
        atomicMax(reinterpret_cast<int*>(&s_amax[c >> 7]), __float_as_int(am));
    }
    for (int i = tid; i < KV_RANK / 4; i += 256) {
        int c = i * 4;
        float4 v = *reinterpret_cast<const float4*>(row + Q_RANK + c);
        float4 w = *reinterpret_cast<const float4*>(wkv + c);
        float4 o;
        o.x = v.x * rkv * w.x;  o.y = v.y * rkv * w.y;
        o.z = v.z * rkv * w.z;  o.w = v.w * rkv * w.w;
        *reinterpret_cast<float4*>(out + OUT_KV + (size_t)m * KV_RANK + c) = o;
    }
    __syncthreads();

    if (tid < N_GROUPS) {
        float sc = fmaxf(s_amax[tid] / FP8_MAX, 1e-12f);
        s_amax[tid] = sc;
        out[OUT_SC + (size_t)m * N_GROUPS + tid] = sc;
    }
    __syncthreads();

    for (int i = tid; i < Q_RANK / 4; i += 256) {
        int c = i * 4;
        float inv = 1.0f / s_amax[c >> 7];
        float4 q = *reinterpret_cast<const float4*>(&s_qn[c]);
        float4 o;
        o.x = q.x * inv; o.y = q.y * inv; o.z = q.z * inv; o.w = q.w * inv;
        *reinterpret_cast<float4*>(out + OUT_QQ + (size_t)m * Q_RANK + c) = o;
    }
}

// ---------------------------------------------------------------------------
extern "C" void kernel_launch(void* const* d_in, const int* in_sizes, int n_in,
                              void* d_out, int out_size)
{
    const float* hidden = (const float*)d_in[0];   // [8192, 7168]
    const float* w_qkv  = (const float*)d_in[1];   // [7168, 2112]
    const float* wq     = (const float*)d_in[2];   // [1536]
    const float* wkv    = (const float*)d_in[3];   // [512]
    float* out = (float*)d_out;

    static bool attr_set = false;
    if (!attr_set) {
        cudaFuncSetAttribute(mma_gemm_kernel,
                             cudaFuncAttributeMaxDynamicSharedMemorySize, SMEM_TOTAL);
        attr_set = true;
    }

    convA_kernel<<<(M_DIM * K_DIM) / (256 * 4), 256>>>(hidden);
    convB_kernel<<<dim3(N_PAD / 32, K_DIM / 32), dim3(32, 8)>>>(w_qkv);
    mma_gemm_kernel<<<dim3(N_PAD / NT, M_DIM / MT), 512, SMEM_TOTAL>>>();
    epilogue_kernel<<<M_DIM, 256>>>(wq, wkv, out);
}